// round 11
// baseline (speedup 1.0000x reference)
#include <cuda_runtime.h>
#include <cstdint>

#define BB 8
#define NN 2048
#define DD 128
#define K_TOP 8
#define TILE 128
#define NT 16
#define PADC 130
#define NEG_INF (-3.402823466e38f)

#define KC 16
#define NCH 8
#define PADM 132              // B tile row pad (floats)
#define PAD2 264              // duplicated-A tile row pad (floats)
#define ADUP_F (KC * PAD2)    // 4224 floats

// smem word offsets (floats)
#define CS_F   (TILE * PADC)          // 16640
#define SGV_O  CS_F                   // [7][256] float
#define SGI_O  (CS_F + 7 * 256)
#define SEI_O  (CS_F + 14 * 256)
#define SM_TOT (CS_F + 22 * 256)      // 22272 words = 89088 B

__device__ float g_normed[BB * NN * DD];
__device__ float g_pval[BB * NN * NT * K_TOP];
__device__ int   g_pidx[BB * NN * NT * K_TOP];

#define FMA2(d, a, b) asm("fma.rn.f32x2 %0, %1, %2, %0;" : "+l"(d) : "l"(a), "l"(b))
__device__ __forceinline__ void upk2(float& lo, float& hi, unsigned long long v) {
    asm("mov.b64 {%0, %1}, %2;" : "=f"(lo), "=f"(hi) : "l"(v));
}

// ---------------------------------------------------------------------------
__global__ void dummy_kernel() {}   // keeps gemm in ncu's profiled slot

__global__ void normalize_kernel(const float* __restrict__ x) {
    int row  = (blockIdx.x * blockDim.x + threadIdx.x) >> 5;
    int lane = threadIdx.x & 31;
    if (row >= BB * NN) return;
    float4 v = ((const float4*)(x + (size_t)row * DD))[lane];
    float s = v.x * v.x + v.y * v.y + v.z * v.z + v.w * v.w;
    #pragma unroll
    for (int o = 16; o; o >>= 1) s += __shfl_xor_sync(0xffffffffu, s, o);
    float nrm = fmaxf(sqrtf(s), 1e-12f);
    float4 ov = make_float4(v.x / nrm, v.y / nrm, v.z / nrm, v.w / nrm);
    ((float4*)(g_normed + (size_t)row * DD))[lane] = ov;
}

__global__ void zero_kernel(float4* __restrict__ out, int n4) {
    int i = blockIdx.x * blockDim.x + threadIdx.x;
    int st = gridDim.x * blockDim.x;
    float4 z = make_float4(0.f, 0.f, 0.f, 0.f);
    for (; i < n4; i += st) out[i] = z;
}

// ---------------------------------------------------------------------------
// two-pass exact top-8: (1) dual independent sorted-8 bubbles (even/odd) +
// cross merge -> exact 8th-largest V8; (2) index recovery, lax.top_k ties.
// ---------------------------------------------------------------------------
__device__ __forceinline__ void scan_topk2(const float* __restrict__ base, int stp,
                                           int ib, int tid, float* sm,
                                           float* __restrict__ pv, int* __restrict__ pi) {
    float sa[8], sb[8];
    #pragma unroll
    for (int k = 0; k < 8; k++) { sa[k] = NEG_INF; sb[k] = NEG_INF; }

    for (int k = 0; k < 64; k++) {       // 2 elements/iter, independent chains
        float va, vb;
        if (stp == 1) {
            float2 v2 = *(const float2*)&base[2 * k];   // LDS.64, 8B aligned
            va = v2.x; vb = v2.y;
        } else {
            va = base[(2 * k) * stp];
            vb = base[(2 * k + 1) * stp];
        }
        sa[0] = fmaxf(sa[0], va);
        sb[0] = fmaxf(sb[0], vb);
        #pragma unroll
        for (int i = 0; i < 7; i++) {
            float alo = fminf(sa[i], sa[i + 1]);
            float ahi = fmaxf(sa[i], sa[i + 1]);
            sa[i] = alo; sa[i + 1] = ahi;
            float blo = fminf(sb[i], sb[i + 1]);
            float bhi = fmaxf(sb[i], sb[i + 1]);
            sb[i] = blo; sb[i + 1] = bhi;
        }
    }
    #pragma unroll
    for (int j = 0; j < 8; j++) {        // merge odd-list into even-list
        sa[0] = fmaxf(sa[0], sb[j]);
        #pragma unroll
        for (int i = 0; i < 7; i++) {
            float lo = fminf(sa[i], sa[i + 1]);
            float hi = fmaxf(sa[i], sa[i + 1]);
            sa[i] = lo; sa[i + 1] = hi;
        }
    }
    float V8 = sa[0];    // exact 8th-largest

    // pass 2: index recovery
    float* sgv = sm + SGV_O;
    int*   sgi = (int*)(sm + SGI_O);
    int*   sei = (int*)(sm + SEI_O);
    int gc = 0, ec = 0;
    for (int k = 0; k < TILE; k++) {
        float v = base[k * stp];
        if (v > V8) {
            sgv[gc * 256 + tid] = v;
            sgi[gc * 256 + tid] = ib + k;
            gc++;
        } else if (v == V8 && ec < 8) {
            sei[ec * 256 + tid] = ib + k;
            ec++;
        }
    }
    #pragma unroll
    for (int q = 0; q < 8; q++) {
        bool g = q < gc;
        int ei = q - gc; if (ei < 0) ei = 0;
        pv[q] = g ? sgv[q * 256 + tid] : V8;
        pi[q] = g ? sgi[q * 256 + tid] : sei[ei * 256 + tid];
    }
}

// ---------------------------------------------------------------------------
// symmetric 128x128 tile: duplicated-A f32x2 GEMM + dual-bubble top-8
// grid (136, 8), 256 threads, 2 CTAs/SM, dyn smem = 89088 B
// ---------------------------------------------------------------------------
__global__ void __launch_bounds__(256, 2) gemm_topk_kernel() {
    extern __shared__ float sm[];
    float* Adup = sm;              // [16][264] duplicated A, k-major
    float* Bst  = sm + ADUP_F;     // [16][132]
    float* Cs   = sm;              // [128][130] overlay

    int b = blockIdx.y;
    int p = blockIdx.x;
    int I = 0;
    while (p >= NT - I) { p -= NT - I; I++; }
    int J = I + p;

    int tid = threadIdx.x;
    int tx = tid & 15, ty = tid >> 4;
    const float* Abase = g_normed + ((size_t)b * NN + (size_t)I * TILE) * DD;
    const float* Bbase = g_normed + ((size_t)b * NN + (size_t)J * TILE) * DD;

    int r0 = tid >> 2, q0 = tid & 3;
    int r1 = (tid + 256) >> 2;

    unsigned long long acc[32];   // [i<8 rows][jp<4 col-pairs]
    #pragma unroll
    for (int i = 0; i < 32; i++) acc[i] = 0ull;

    float4 vA0 = *(const float4*)(Abase + r0 * DD + q0 * 4);
    float4 vA1 = *(const float4*)(Abase + r1 * DD + q0 * 4);
    float4 vB0 = *(const float4*)(Bbase + r0 * DD + q0 * 4);
    float4 vB1 = *(const float4*)(Bbase + r1 * DD + q0 * 4);

    for (int c = 0; c < NCH; c++) {
        {
            float av0[4] = {vA0.x, vA0.y, vA0.z, vA0.w};
            float av1[4] = {vA1.x, vA1.y, vA1.z, vA1.w};
            float bv0[4] = {vB0.x, vB0.y, vB0.z, vB0.w};
            float bv1[4] = {vB1.x, vB1.y, vB1.z, vB1.w};
            #pragma unroll
            for (int e = 0; e < 4; e++) {
                int k = q0 * 4 + e;
                *(float2*)&Adup[k * PAD2 + 2 * r0] = make_float2(av0[e], av0[e]);
                *(float2*)&Adup[k * PAD2 + 2 * r1] = make_float2(av1[e], av1[e]);
                Bst[k * PADM + r0] = bv0[e];
                Bst[k * PADM + r1] = bv1[e];
            }
        }
        __syncthreads();

        if (c + 1 < NCH) {
            int k0 = (c + 1) * KC;
            vA0 = *(const float4*)(Abase + r0 * DD + k0 + q0 * 4);
            vA1 = *(const float4*)(Abase + r1 * DD + k0 + q0 * 4);
            vB0 = *(const float4*)(Bbase + r0 * DD + k0 + q0 * 4);
            vB1 = *(const float4*)(Bbase + r1 * DD + k0 + q0 * 4);
        }

        #pragma unroll
        for (int k = 0; k < KC; k++) {
            const float* Ak = Adup + k * PAD2;
            const float* Bk = Bst + k * PADM;
            ulonglong2 adA = *(const ulonglong2*)&Ak[8 * ty];          // rows ty*4+0,1
            ulonglong2 adB = *(const ulonglong2*)&Ak[8 * ty + 4];      // rows ty*4+2,3
            ulonglong2 adC = *(const ulonglong2*)&Ak[128 + 8 * ty];    // rows 64+...
            ulonglong2 adD = *(const ulonglong2*)&Ak[128 + 8 * ty + 4];
            ulonglong2 b01 = *(const ulonglong2*)&Bk[tx * 4];          // col pairs 0,1
            ulonglong2 b23 = *(const ulonglong2*)&Bk[64 + tx * 4];     // col pairs 2,3
            unsigned long long ad[8] = {adA.x, adA.y, adB.x, adB.y,
                                        adC.x, adC.y, adD.x, adD.y};
            unsigned long long bp[4] = {b01.x, b01.y, b23.x, b23.y};
            #pragma unroll
            for (int i = 0; i < 8; i++) {
                FMA2(acc[i * 4 + 0], ad[i], bp[0]);
                FMA2(acc[i * 4 + 1], ad[i], bp[1]);
                FMA2(acc[i * 4 + 2], ad[i], bp[2]);
                FMA2(acc[i * 4 + 3], ad[i], bp[3]);
            }
        }
        __syncthreads();
    }

    // write scores
    #pragma unroll
    for (int i = 0; i < 8; i++) {
        int row = (i < 4) ? (ty * 4 + i) : (64 + ty * 4 + i - 4);
        #pragma unroll
        for (int jp = 0; jp < 4; jp++) {
            int col = (jp < 2) ? (tx * 4 + jp * 2) : (64 + tx * 4 + (jp - 2) * 2);
            float lo, hi;
            upk2(lo, hi, acc[i * 4 + jp]);
            Cs[row * PADC + col]     = lo;
            Cs[row * PADC + col + 1] = hi;
        }
    }
    __syncthreads();

    if (tid < 128) {
        size_t grow = (size_t)b * NN + (size_t)I * TILE + tid;
        scan_topk2(Cs + tid * PADC, 1, J * TILE, tid, sm,
                   g_pval + (grow * NT + J) * K_TOP,
                   g_pidx + (grow * NT + J) * K_TOP);
    } else if (I != J) {
        int cc = tid - 128;
        size_t grow = (size_t)b * NN + (size_t)J * TILE + cc;
        scan_topk2(Cs + cc, PADC, I * TILE, tid, sm,
                   g_pval + (grow * NT + I) * K_TOP,
                   g_pidx + (grow * NT + I) * K_TOP);
    }
}

// ---------------------------------------------------------------------------
__global__ void merge_scatter_kernel(float* __restrict__ out) {
    int gw   = (blockIdx.x * blockDim.x + threadIdx.x) >> 5;
    int lane = threadIdx.x & 31;
    if (gw >= BB * NN) return;
    int b = gw / NN, n = gw % NN;
    const float* pv = g_pval + (size_t)gw * NT * K_TOP;
    const int*   pi = g_pidx + (size_t)gw * NT * K_TOP;
    float v[4]; int id[4];
    #pragma unroll
    for (int q = 0; q < 4; q++) {
        v[q]  = pv[lane + 32 * q];
        id[q] = pi[lane + 32 * q];
    }
    float* base = out + (size_t)b * NN * NN;
    #pragma unroll
    for (int t = 0; t < K_TOP; t++) {
        float bv = v[0]; int bi = id[0];
        #pragma unroll
        for (int q = 1; q < 4; q++)
            if (v[q] > bv || (v[q] == bv && id[q] < bi)) { bv = v[q]; bi = id[q]; }
        #pragma unroll
        for (int off = 16; off; off >>= 1) {
            float ov = __shfl_xor_sync(0xffffffffu, bv, off);
            int   oi = __shfl_xor_sync(0xffffffffu, bi, off);
            if (ov > bv || (ov == bv && oi < bi)) { bv = ov; bi = oi; }
        }
        if (lane == t) {
            base[(size_t)n * NN + bi] = 1.0f;
            base[(size_t)bi * NN + n] = 1.0f;
        }
        #pragma unroll
        for (int q = 0; q < 4; q++)
            if (id[q] == bi) v[q] = NEG_INF;
    }
    if (lane == 8) base[(size_t)n * NN + n] = 1.0f;
}

// ---------------------------------------------------------------------------
extern "C" void kernel_launch(void* const* d_in, const int* in_sizes, int n_in,
                              void* d_out, int out_size) {
    const float* x = (const float*)d_in[0];
    float* out = (float*)d_out;

    int smem = SM_TOT * 4;   // 89088
    cudaFuncSetAttribute(gemm_topk_kernel,
                         cudaFuncAttributeMaxDynamicSharedMemorySize, smem);

    dummy_kernel<<<1, 32>>>();
    normalize_kernel<<<(BB * NN) / 8, 256>>>(x);
    zero_kernel<<<8192, 256>>>((float4*)out, out_size / 4);
    gemm_topk_kernel<<<dim3(NT * (NT + 1) / 2, BB), 256, smem>>>();
    merge_scatter_kernel<<<(BB * NN) / 8, 256>>>(out);
}

// round 12
// speedup vs baseline: 1.0619x; 1.0619x over previous
#include <cuda_runtime.h>
#include <cstdint>

#define BB 8
#define NN 2048
#define DD 128
#define K_TOP 8
#define TILE 128
#define NT 16
#define PADC 130
#define NEG_INF (-3.402823466e38f)

#define KC 16
#define NCH 8
#define PADM 132              // staged tile row pad (floats)
#define AST_F (KC * PADM)     // 2112 floats per tile

// smem word offsets (floats)
#define CS_F   (TILE * PADC)          // 16640
#define SGV_O  CS_F                   // [7][256] float
#define SGI_O  (CS_F + 7 * 256)
#define SEI_O  (CS_F + 14 * 256)
#define SM_TOT (CS_F + 22 * 256)      // 22272 words = 89088 B

__device__ float g_normed[BB * NN * DD];
__device__ float g_pval[BB * NN * NT * K_TOP];
__device__ int   g_pidx[BB * NN * NT * K_TOP];

#define FMA2(d, a, b) asm("fma.rn.f32x2 %0, %1, %2, %0;" : "+l"(d) : "l"(a), "l"(b))
__device__ __forceinline__ unsigned long long pk2(float lo, float hi) {
    unsigned long long d;
    asm("mov.b64 %0, {%1, %2};" : "=l"(d) : "f"(lo), "f"(hi));
    return d;
}
__device__ __forceinline__ void upk2(float& lo, float& hi, unsigned long long v) {
    asm("mov.b64 {%0, %1}, %2;" : "=f"(lo), "=f"(hi) : "l"(v));
}

// ---------------------------------------------------------------------------
__global__ void dummy_kernel() {}   // keeps gemm in ncu's profiled slot

__global__ void normalize_kernel(const float* __restrict__ x) {
    int row  = (blockIdx.x * blockDim.x + threadIdx.x) >> 5;
    int lane = threadIdx.x & 31;
    if (row >= BB * NN) return;
    float4 v = ((const float4*)(x + (size_t)row * DD))[lane];
    float s = v.x * v.x + v.y * v.y + v.z * v.z + v.w * v.w;
    #pragma unroll
    for (int o = 16; o; o >>= 1) s += __shfl_xor_sync(0xffffffffu, s, o);
    float nrm = fmaxf(sqrtf(s), 1e-12f);
    float4 ov = make_float4(v.x / nrm, v.y / nrm, v.z / nrm, v.w / nrm);
    ((float4*)(g_normed + (size_t)row * DD))[lane] = ov;
}

__global__ void zero_kernel(float4* __restrict__ out, int n4) {
    int i = blockIdx.x * blockDim.x + threadIdx.x;
    int st = gridDim.x * blockDim.x;
    float4 z = make_float4(0.f, 0.f, 0.f, 0.f);
    for (; i < n4; i += st) out[i] = z;
}

// ---------------------------------------------------------------------------
// two-pass exact top-8: dual independent sorted-8 bubbles + cross merge,
// then index recovery with exact lax.top_k tie semantics.
// ---------------------------------------------------------------------------
__device__ __forceinline__ void scan_topk2(const float* __restrict__ base, int stp,
                                           int ib, int tid, float* sm,
                                           float* __restrict__ pv, int* __restrict__ pi) {
    float sa[8], sb[8];
    #pragma unroll
    for (int k = 0; k < 8; k++) { sa[k] = NEG_INF; sb[k] = NEG_INF; }

    for (int k = 0; k < 64; k++) {
        float va, vb;
        if (stp == 1) {
            float2 v2 = *(const float2*)&base[2 * k];
            va = v2.x; vb = v2.y;
        } else {
            va = base[(2 * k) * stp];
            vb = base[(2 * k + 1) * stp];
        }
        sa[0] = fmaxf(sa[0], va);
        sb[0] = fmaxf(sb[0], vb);
        #pragma unroll
        for (int i = 0; i < 7; i++) {
            float alo = fminf(sa[i], sa[i + 1]);
            float ahi = fmaxf(sa[i], sa[i + 1]);
            sa[i] = alo; sa[i + 1] = ahi;
            float blo = fminf(sb[i], sb[i + 1]);
            float bhi = fmaxf(sb[i], sb[i + 1]);
            sb[i] = blo; sb[i + 1] = bhi;
        }
    }
    #pragma unroll
    for (int j = 0; j < 8; j++) {
        sa[0] = fmaxf(sa[0], sb[j]);
        #pragma unroll
        for (int i = 0; i < 7; i++) {
            float lo = fminf(sa[i], sa[i + 1]);
            float hi = fmaxf(sa[i], sa[i + 1]);
            sa[i] = lo; sa[i + 1] = hi;
        }
    }
    float V8 = sa[0];

    float* sgv = sm + SGV_O;
    int*   sgi = (int*)(sm + SGI_O);
    int*   sei = (int*)(sm + SEI_O);
    int gc = 0, ec = 0;
    for (int k = 0; k < TILE; k++) {
        float v = base[k * stp];
        if (v > V8) {
            sgv[gc * 256 + tid] = v;
            sgi[gc * 256 + tid] = ib + k;
            gc++;
        } else if (v == V8 && ec < 8) {
            sei[ec * 256 + tid] = ib + k;
            ec++;
        }
    }
    #pragma unroll
    for (int q = 0; q < 8; q++) {
        bool g = q < gc;
        int ei = q - gc; if (ei < 0) ei = 0;
        pv[q] = g ? sgv[q * 256 + tid] : V8;
        pi[q] = g ? sgi[q * 256 + tid] : sei[ei * 256 + tid];
    }
}

// ---------------------------------------------------------------------------
// symmetric 128x128 tile: 512-thread transposed-smem f32x2 GEMM + top-8
// grid (136, 8), 512 threads, 2 CTAs/SM (occ 50%), dyn smem = 89088 B
// ---------------------------------------------------------------------------
__global__ void __launch_bounds__(512, 2) gemm_topk_kernel() {
    extern __shared__ float sm[];
    float* Ast = sm;              // [16][132] k-major
    float* Bst = sm + AST_F;      // [16][132]
    float* Cs  = sm;              // [128][130] overlay

    int b = blockIdx.y;
    int p = blockIdx.x;
    int I = 0;
    while (p >= NT - I) { p -= NT - I; I++; }
    int J = I + p;

    int tid = threadIdx.x;
    int tx = tid & 15, ty = tid >> 4;   // ty 0..31: rows ty*4..+3; tx: cols tx*4(+64)
    const float* Abase = g_normed + ((size_t)b * NN + (size_t)I * TILE) * DD;
    const float* Bbase = g_normed + ((size_t)b * NN + (size_t)J * TILE) * DD;

    // staging: thread -> one A float4 + one B float4 per chunk
    int r0 = tid >> 2, q0 = tid & 3;

    unsigned long long acc[16];   // [i<4 rows][jp<4 col-pairs]
    #pragma unroll
    for (int i = 0; i < 16; i++) acc[i] = 0ull;

    float4 vA = *(const float4*)(Abase + r0 * DD + q0 * 4);
    float4 vB = *(const float4*)(Bbase + r0 * DD + q0 * 4);

    for (int c = 0; c < NCH; c++) {
        // store staged regs transposed: Ast[(q*4+e)][r]
        Ast[(q0 * 4 + 0) * PADM + r0] = vA.x;
        Ast[(q0 * 4 + 1) * PADM + r0] = vA.y;
        Ast[(q0 * 4 + 2) * PADM + r0] = vA.z;
        Ast[(q0 * 4 + 3) * PADM + r0] = vA.w;
        Bst[(q0 * 4 + 0) * PADM + r0] = vB.x;
        Bst[(q0 * 4 + 1) * PADM + r0] = vB.y;
        Bst[(q0 * 4 + 2) * PADM + r0] = vB.z;
        Bst[(q0 * 4 + 3) * PADM + r0] = vB.w;
        __syncthreads();

        if (c + 1 < NCH) {
            int k0 = (c + 1) * KC;
            vA = *(const float4*)(Abase + r0 * DD + k0 + q0 * 4);
            vB = *(const float4*)(Bbase + r0 * DD + k0 + q0 * 4);
        }

        #pragma unroll
        for (int k = 0; k < KC; k++) {
            float4 a4 = *(const float4*)&Ast[k * PADM + ty * 4];
            float4 b0 = *(const float4*)&Bst[k * PADM + tx * 4];
            float4 b1 = *(const float4*)&Bst[k * PADM + 64 + tx * 4];
            unsigned long long bp[4];
            bp[0] = pk2(b0.x, b0.y); bp[1] = pk2(b0.z, b0.w);
            bp[2] = pk2(b1.x, b1.y); bp[3] = pk2(b1.z, b1.w);
            float av[4] = {a4.x, a4.y, a4.z, a4.w};
            #pragma unroll
            for (int i = 0; i < 4; i++) {
                unsigned long long ad = pk2(av[i], av[i]);
                FMA2(acc[i * 4 + 0], ad, bp[0]);
                FMA2(acc[i * 4 + 1], ad, bp[1]);
                FMA2(acc[i * 4 + 2], ad, bp[2]);
                FMA2(acc[i * 4 + 3], ad, bp[3]);
            }
        }
        __syncthreads();
    }

    // write scores: rows ty*4+i, col pairs tx*4 / 64+tx*4
    #pragma unroll
    for (int i = 0; i < 4; i++) {
        int row = ty * 4 + i;
        #pragma unroll
        for (int jp = 0; jp < 4; jp++) {
            int col = (jp < 2) ? (tx * 4 + jp * 2) : (64 + tx * 4 + (jp - 2) * 2);
            float lo, hi;
            upk2(lo, hi, acc[i * 4 + jp]);
            Cs[row * PADC + col]     = lo;
            Cs[row * PADC + col + 1] = hi;
        }
    }
    __syncthreads();

    if (tid < 128) {
        size_t grow = (size_t)b * NN + (size_t)I * TILE + tid;
        scan_topk2(Cs + tid * PADC, 1, J * TILE, tid, sm,
                   g_pval + (grow * NT + J) * K_TOP,
                   g_pidx + (grow * NT + J) * K_TOP);
    } else if (tid < 256 && I != J) {
        int cc = tid - 128;
        size_t grow = (size_t)b * NN + (size_t)J * TILE + cc;
        scan_topk2(Cs + cc, PADC, I * TILE, tid, sm,
                   g_pval + (grow * NT + I) * K_TOP,
                   g_pidx + (grow * NT + I) * K_TOP);
    }
}

// ---------------------------------------------------------------------------
__global__ void merge_scatter_kernel(float* __restrict__ out) {
    int gw   = (blockIdx.x * blockDim.x + threadIdx.x) >> 5;
    int lane = threadIdx.x & 31;
    if (gw >= BB * NN) return;
    int b = gw / NN, n = gw % NN;
    const float* pv = g_pval + (size_t)gw * NT * K_TOP;
    const int*   pi = g_pidx + (size_t)gw * NT * K_TOP;
    float v[4]; int id[4];
    #pragma unroll
    for (int q = 0; q < 4; q++) {
        v[q]  = pv[lane + 32 * q];
        id[q] = pi[lane + 32 * q];
    }
    float* base = out + (size_t)b * NN * NN;
    #pragma unroll
    for (int t = 0; t < K_TOP; t++) {
        float bv = v[0]; int bi = id[0];
        #pragma unroll
        for (int q = 1; q < 4; q++)
            if (v[q] > bv || (v[q] == bv && id[q] < bi)) { bv = v[q]; bi = id[q]; }
        #pragma unroll
        for (int off = 16; off; off >>= 1) {
            float ov = __shfl_xor_sync(0xffffffffu, bv, off);
            int   oi = __shfl_xor_sync(0xffffffffu, bi, off);
            if (ov > bv || (ov == bv && oi < bi)) { bv = ov; bi = oi; }
        }
        if (lane == t) {
            base[(size_t)n * NN + bi] = 1.0f;
            base[(size_t)bi * NN + n] = 1.0f;
        }
        #pragma unroll
        for (int q = 0; q < 4; q++)
            if (id[q] == bi) v[q] = NEG_INF;
    }
    if (lane == 8) base[(size_t)n * NN + n] = 1.0f;
}

// ---------------------------------------------------------------------------
extern "C" void kernel_launch(void* const* d_in, const int* in_sizes, int n_in,
                              void* d_out, int out_size) {
    const float* x = (const float*)d_in[0];
    float* out = (float*)d_out;

    int smem = SM_TOT * 4;   // 89088
    cudaFuncSetAttribute(gemm_topk_kernel,
                         cudaFuncAttributeMaxDynamicSharedMemorySize, smem);

    dummy_kernel<<<1, 32>>>();
    normalize_kernel<<<(BB * NN) / 8, 256>>>(x);
    zero_kernel<<<8192, 256>>>((float4*)out, out_size / 4);
    gemm_topk_kernel<<<dim3(NT * (NT + 1) / 2, BB), 512, smem>>>();
    merge_scatter_kernel<<<(BB * NN) / 8, 256>>>(out);
}

// round 13
// speedup vs baseline: 1.1605x; 1.0929x over previous
#include <cuda_runtime.h>
#include <cstdint>

#define BB 8
#define NN 2048
#define DD 128
#define K_TOP 8
#define TILE 128
#define NT 16
#define PADC 132
#define NEG_INF (-3.402823466e38f)

#define KC 16
#define NCH 8
#define PAD2 260              // duplicated-A row pad (floats), mult of 4
#define PADM 132              // B row pad
#define ADUP_F (KC * PAD2)    // 4160

// smem word offsets (floats)
#define CS_F   (TILE * PADC)          // 16896
#define SGV_O  CS_F
#define SGI_O  (CS_F + 7 * 256)
#define SEI_O  (CS_F + 14 * 256)
#define SM_TOT (CS_F + 22 * 256)      // 22528 words = 90112 B

__device__ float g_normed[BB * NN * DD];
__device__ float g_pval[BB * NN * NT * K_TOP];
__device__ int   g_pidx[BB * NN * NT * K_TOP];

#define FMA2(d, a, b) asm("fma.rn.f32x2 %0, %1, %2, %0;" : "+l"(d) : "l"(a), "l"(b))
__device__ __forceinline__ void upk2(float& lo, float& hi, unsigned long long v) {
    asm("mov.b64 {%0, %1}, %2;" : "=f"(lo), "=f"(hi) : "l"(v));
}
#define CASF(a, b) { float _t = fminf(a, b); b = fmaxf(a, b); a = _t; }

// ---------------------------------------------------------------------------
__global__ void dummy_kernel() {}   // keeps gemm in ncu's profiled slot

__global__ void normalize_kernel(const float* __restrict__ x) {
    int row  = (blockIdx.x * blockDim.x + threadIdx.x) >> 5;
    int lane = threadIdx.x & 31;
    if (row >= BB * NN) return;
    float4 v = ((const float4*)(x + (size_t)row * DD))[lane];
    float s = v.x * v.x + v.y * v.y + v.z * v.z + v.w * v.w;
    #pragma unroll
    for (int o = 16; o; o >>= 1) s += __shfl_xor_sync(0xffffffffu, s, o);
    float nrm = fmaxf(sqrtf(s), 1e-12f);
    float4 ov = make_float4(v.x / nrm, v.y / nrm, v.z / nrm, v.w / nrm);
    ((float4*)(g_normed + (size_t)row * DD))[lane] = ov;
}

// ---------------------------------------------------------------------------
// two-pass exact top-8: (1) per-8 sorting network + bitonic top-8 merge,
// (2) index recovery with exact lax.top_k tie semantics.
// ---------------------------------------------------------------------------
__device__ __forceinline__ void scan_topk2(const float* __restrict__ base, int stp,
                                           int ib, int tid, float* sm,
                                           float* __restrict__ pv, int* __restrict__ pi) {
    float s[8];
    #pragma unroll
    for (int k = 0; k < 8; k++) s[k] = NEG_INF;

    for (int g = 0; g < 16; g++) {
        float e[8];
        if (stp == 1) {
            float4 v0 = *(const float4*)&base[8 * g];
            float4 v1 = *(const float4*)&base[8 * g + 4];
            e[0] = v0.x; e[1] = v0.y; e[2] = v0.z; e[3] = v0.w;
            e[4] = v1.x; e[5] = v1.y; e[6] = v1.z; e[7] = v1.w;
        } else {
            #pragma unroll
            for (int j = 0; j < 8; j++) e[j] = base[(8 * g + j) * stp];
        }
        // Batcher odd-even mergesort 8 (19 CAS) -> ascending
        CASF(e[0], e[1]) CASF(e[2], e[3]) CASF(e[4], e[5]) CASF(e[6], e[7])
        CASF(e[0], e[2]) CASF(e[1], e[3]) CASF(e[4], e[6]) CASF(e[5], e[7])
        CASF(e[1], e[2]) CASF(e[5], e[6])
        CASF(e[0], e[4]) CASF(e[1], e[5]) CASF(e[2], e[6]) CASF(e[3], e[7])
        CASF(e[2], e[4]) CASF(e[3], e[5])
        CASF(e[1], e[2]) CASF(e[3], e[4]) CASF(e[5], e[6])
        // top-8 of (s ∪ e): pair max -> bitonic
        #pragma unroll
        for (int i = 0; i < 8; i++) s[i] = fmaxf(s[i], e[7 - i]);
        // bitonic -> ascending (12 CAS)
        CASF(s[0], s[4]) CASF(s[1], s[5]) CASF(s[2], s[6]) CASF(s[3], s[7])
        CASF(s[0], s[2]) CASF(s[1], s[3]) CASF(s[4], s[6]) CASF(s[5], s[7])
        CASF(s[0], s[1]) CASF(s[2], s[3]) CASF(s[4], s[5]) CASF(s[6], s[7])
    }
    float V8 = s[0];   // exact 8th-largest

    float* sgv = sm + SGV_O;
    int*   sgi = (int*)(sm + SGI_O);
    int*   sei = (int*)(sm + SEI_O);
    int gc = 0, ec = 0;
    for (int k = 0; k < TILE; k++) {
        float v = base[k * stp];
        if (v > V8) {
            sgv[gc * 256 + tid] = v;
            sgi[gc * 256 + tid] = ib + k;
            gc++;
        } else if (v == V8 && ec < 8) {
            sei[ec * 256 + tid] = ib + k;
            ec++;
        }
    }
    #pragma unroll
    for (int q = 0; q < 8; q++) {
        bool g = q < gc;
        int ei = q - gc; if (ei < 0) ei = 0;
        pv[q] = g ? sgv[q * 256 + tid] : V8;
        pi[q] = g ? sgi[q * 256 + tid] : sei[ei * 256 + tid];
    }
}

// ---------------------------------------------------------------------------
// symmetric 128x128 tile: dup-A smem f32x2 GEMM + network top-8 + zero-fold
// grid (136, 8), 256 threads, 2 CTAs/SM, dyn smem = 90112 B
// ---------------------------------------------------------------------------
__global__ void __launch_bounds__(256, 2) gemm_topk_kernel(float* __restrict__ out,
                                                           int out_n4) {
    extern __shared__ float sm[];
    float* Adup = sm;              // [16][260]: Adup[k][2m]=Adup[k][2m+1]=A[m][k]
    float* Bst  = sm + ADUP_F;     // [16][132] k-major
    float* Cs   = sm;              // [128][132] overlay

    int b = blockIdx.y;
    int p = blockIdx.x;
    int I = 0;
    while (p >= NT - I) { p -= NT - I; I++; }
    int J = I + p;

    int tid = threadIdx.x;
    int tx = tid & 15, ty = tid >> 4;
    const float* Abase = g_normed + ((size_t)b * NN + (size_t)I * TILE) * DD;
    const float* Bbase = g_normed + ((size_t)b * NN + (size_t)J * TILE) * DD;

    // ---- fold: zero a slice of the output (independent; hides under compute)
    {
        int cta = blockIdx.y * gridDim.x + blockIdx.x;
        float4 z = make_float4(0.f, 0.f, 0.f, 0.f);
        float4* o4 = (float4*)out;
        for (int i = cta * 256 + tid; i < out_n4; i += 1088 * 256)
            o4[i] = z;
    }

    int r0 = tid >> 2, q0 = tid & 3;
    int r1 = r0 + 64;

    unsigned long long acc[32];   // [i<8 rows][jp<4 col-pairs]
    #pragma unroll
    for (int i = 0; i < 32; i++) acc[i] = 0ull;

    float4 vA0 = *(const float4*)(Abase + r0 * DD + q0 * 4);
    float4 vA1 = *(const float4*)(Abase + r1 * DD + q0 * 4);
    float4 vB0 = *(const float4*)(Bbase + r0 * DD + q0 * 4);
    float4 vB1 = *(const float4*)(Bbase + r1 * DD + q0 * 4);

    for (int c = 0; c < NCH; c++) {
        {
            float a0[4] = {vA0.x, vA0.y, vA0.z, vA0.w};
            float a1[4] = {vA1.x, vA1.y, vA1.z, vA1.w};
            float b0[4] = {vB0.x, vB0.y, vB0.z, vB0.w};
            float b1[4] = {vB1.x, vB1.y, vB1.z, vB1.w};
            #pragma unroll
            for (int e = 0; e < 4; e++) {
                int k = q0 * 4 + e;
                *(float2*)&Adup[k * PAD2 + 2 * r0] = make_float2(a0[e], a0[e]);
                *(float2*)&Adup[k * PAD2 + 2 * r1] = make_float2(a1[e], a1[e]);
                Bst[k * PADM + r0] = b0[e];
                Bst[k * PADM + r1] = b1[e];
            }
        }
        __syncthreads();

        if (c + 1 < NCH) {
            int k0 = (c + 1) * KC;
            vA0 = *(const float4*)(Abase + r0 * DD + k0 + q0 * 4);
            vA1 = *(const float4*)(Abase + r1 * DD + k0 + q0 * 4);
            vB0 = *(const float4*)(Bbase + r0 * DD + k0 + q0 * 4);
            vB1 = *(const float4*)(Bbase + r1 * DD + k0 + q0 * 4);
        }

        #pragma unroll
        for (int k = 0; k < KC; k++) {
            const float* Ak = Adup + k * PAD2 + 16 * ty;   // rows 8ty..8ty+7 dup'd
            const float* Bk = Bst + k * PADM;
            ulonglong2 aA = *(const ulonglong2*)&Ak[0];    // (a0,a0),(a1,a1)
            ulonglong2 aB = *(const ulonglong2*)&Ak[4];    // (a2,a2),(a3,a3)
            ulonglong2 aC = *(const ulonglong2*)&Ak[8];
            ulonglong2 aD = *(const ulonglong2*)&Ak[12];
            ulonglong2 b01 = *(const ulonglong2*)&Bk[tx * 4];
            ulonglong2 b23 = *(const ulonglong2*)&Bk[64 + tx * 4];
            unsigned long long ad[8] = {aA.x, aA.y, aB.x, aB.y, aC.x, aC.y, aD.x, aD.y};
            unsigned long long bp[4] = {b01.x, b01.y, b23.x, b23.y};
            #pragma unroll
            for (int i = 0; i < 8; i++) {
                FMA2(acc[i * 4 + 0], ad[i], bp[0]);
                FMA2(acc[i * 4 + 1], ad[i], bp[1]);
                FMA2(acc[i * 4 + 2], ad[i], bp[2]);
                FMA2(acc[i * 4 + 3], ad[i], bp[3]);
            }
        }
        __syncthreads();
    }

    // write scores: rows 8ty+i, col pairs tx*4 / 64+tx*4
    #pragma unroll
    for (int i = 0; i < 8; i++) {
        int row = ty * 8 + i;
        #pragma unroll
        for (int jp = 0; jp < 4; jp++) {
            int col = (jp < 2) ? (tx * 4 + jp * 2) : (64 + tx * 4 + (jp - 2) * 2);
            float lo, hi;
            upk2(lo, hi, acc[i * 4 + jp]);
            *(float2*)&Cs[row * PADC + col] = make_float2(lo, hi);
        }
    }
    __syncthreads();

    if (tid < 128) {
        size_t grow = (size_t)b * NN + (size_t)I * TILE + tid;
        scan_topk2(Cs + tid * PADC, 1, J * TILE, tid, sm,
                   g_pval + (grow * NT + J) * K_TOP,
                   g_pidx + (grow * NT + J) * K_TOP);
    } else if (I != J) {
        int cc = tid - 128;
        size_t grow = (size_t)b * NN + (size_t)J * TILE + cc;
        scan_topk2(Cs + cc, PADC, I * TILE, tid, sm,
                   g_pval + (grow * NT + I) * K_TOP,
                   g_pidx + (grow * NT + I) * K_TOP);
    }
}

// ---------------------------------------------------------------------------
__global__ void merge_scatter_kernel(float* __restrict__ out) {
    int gw   = (blockIdx.x * blockDim.x + threadIdx.x) >> 5;
    int lane = threadIdx.x & 31;
    if (gw >= BB * NN) return;
    int b = gw / NN, n = gw % NN;
    const float* pv = g_pval + (size_t)gw * NT * K_TOP;
    const int*   pi = g_pidx + (size_t)gw * NT * K_TOP;
    float v[4]; int id[4];
    #pragma unroll
    for (int q = 0; q < 4; q++) {
        v[q]  = pv[lane + 32 * q];
        id[q] = pi[lane + 32 * q];
    }
    float* base = out + (size_t)b * NN * NN;
    #pragma unroll
    for (int t = 0; t < K_TOP; t++) {
        float bv = v[0]; int bi = id[0];
        #pragma unroll
        for (int q = 1; q < 4; q++)
            if (v[q] > bv || (v[q] == bv && id[q] < bi)) { bv = v[q]; bi = id[q]; }
        #pragma unroll
        for (int off = 16; off; off >>= 1) {
            float ov = __shfl_xor_sync(0xffffffffu, bv, off);
            int   oi = __shfl_xor_sync(0xffffffffu, bi, off);
            if (ov > bv || (ov == bv && oi < bi)) { bv = ov; bi = oi; }
        }
        if (lane == t) {
            base[(size_t)n * NN + bi] = 1.0f;
            base[(size_t)bi * NN + n] = 1.0f;
        }
        #pragma unroll
        for (int q = 0; q < 4; q++)
            if (id[q] == bi) v[q] = NEG_INF;
    }
    if (lane == 8) base[(size_t)n * NN + n] = 1.0f;
}

// ---------------------------------------------------------------------------
extern "C" void kernel_launch(void* const* d_in, const int* in_sizes, int n_in,
                              void* d_out, int out_size) {
    const float* x = (const float*)d_in[0];
    float* out = (float*)d_out;

    int smem = SM_TOT * 4;   // 90112
    cudaFuncSetAttribute(gemm_topk_kernel,
                         cudaFuncAttributeMaxDynamicSharedMemorySize, smem);

    dummy_kernel<<<1, 32>>>();
    normalize_kernel<<<(BB * NN) / 8, 256>>>(x);
    dummy_kernel<<<1, 32>>>();   // keep gemm at the same launch index as before
    gemm_topk_kernel<<<dim3(NT * (NT + 1) / 2, BB), 256, smem>>>(out, out_size / 4);
    merge_scatter_kernel<<<(BB * NN) / 8, 256>>>(out);
}